// round 3
// baseline (speedup 1.0000x reference)
#include <cuda_runtime.h>
#include <cstdint>

// PoolingLayer: out[p, f] = max_k features[idx[p,k], f]
// NP=50000, K=32, F=128. features: (100000,128) f32.
// idx: (50000,32), dtype int32 (JAX x64-disabled downgrades jnp.int64) —
// detected at runtime to be safe either way.

#define NP_POINTS 50000
#define N_POINTS  100000
#define K_NEIGH   32
#define F_VEC4    32   // 128 floats = 32 float4

#define SZ_FEATURES 12800000   // 100000 * 128 f32
#define SZ_INDICES  1600000    // 50000 * 32

// 1 -> indices are int64, 0 -> int32
__device__ int g_idx_is_64;

__global__ void detect_idx_dtype(const int* __restrict__ idx_raw)
{
    // int64 values < 2^31 stored little-endian: every odd 32-bit word is 0.
    // Genuine random int32 indices in [0,1e5): P(64 consecutive odd words all 0) ~ 0.
    if (threadIdx.x == 0) {
        int all_zero = 1;
        #pragma unroll 1
        for (int i = 0; i < 64; ++i) {
            if (idx_raw[2 * i + 1] != 0) { all_zero = 0; break; }
        }
        g_idx_is_64 = all_zero;
    }
}

template <bool IDX64>
__global__ __launch_bounds__(256, 8)
void pool_max_kernel(const float4* __restrict__ feat,
                     const void* __restrict__ idx_raw,
                     float4* __restrict__ out)
{
    // Early-exit if the detected dtype doesn't match this instantiation.
    if (g_idx_is_64 != (IDX64 ? 1 : 0)) return;

    const int gtid = blockIdx.x * blockDim.x + threadIdx.x;
    const int warp = gtid >> 5;
    const int lane = gtid & 31;
    if (warp >= NP_POINTS) return;

    // Coalesced index load: lane l holds neighbor index l for this point.
    long long my_idx;
    if (IDX64) {
        my_idx = ((const long long*)idx_raw)[(long long)warp * K_NEIGH + lane];
    } else {
        my_idx = ((const int*)idx_raw)[warp * K_NEIGH + lane];
    }
    // Clamp: never crash on a format surprise (turns it into a rel_err signal).
    if (my_idx < 0) my_idx = 0;
    if (my_idx >= N_POINTS) my_idx = N_POINTS - 1;

    float4 m;
    m.x = -__int_as_float(0x7f800000);  // -inf
    m.y = m.x; m.z = m.x; m.w = m.x;

    #pragma unroll
    for (int k = 0; k < K_NEIGH; ++k) {
        const long long j = __shfl_sync(0xffffffffu, my_idx, k);
        const float4 v = __ldg(&feat[j * F_VEC4 + lane]);
        m.x = fmaxf(m.x, v.x);
        m.y = fmaxf(m.y, v.y);
        m.z = fmaxf(m.z, v.z);
        m.w = fmaxf(m.w, v.w);
    }

    out[(long long)warp * F_VEC4 + lane] = m;
}

extern "C" void kernel_launch(void* const* d_in, const int* in_sizes, int n_in,
                              void* d_out, int out_size)
{
    // Resolve inputs by element count (order-independent):
    //   features : 12800000 f32
    //   indices  : 1600000 (int32 or int64)
    const float4* feat    = nullptr;
    const void*   idx_raw = nullptr;
    for (int i = 0; i < n_in; ++i) {
        if (in_sizes[i] == SZ_FEATURES)     feat    = (const float4*)d_in[i];
        else if (in_sizes[i] == SZ_INDICES) idx_raw = d_in[i];
    }
    if (!feat)    feat    = (const float4*)d_in[1];
    if (!idx_raw) idx_raw = d_in[2];

    float4* out = (float4*)d_out;

    detect_idx_dtype<<<1, 32>>>((const int*)idx_raw);

    const int total_threads = NP_POINTS * 32;   // one warp per point
    const int block = 256;
    const int grid = (total_threads + block - 1) / block;  // 6250
    pool_max_kernel<false><<<grid, block>>>(feat, idx_raw, out);
    pool_max_kernel<true ><<<grid, block>>>(feat, idx_raw, out);
}

// round 5
// speedup vs baseline: 1.4649x; 1.4649x over previous
#include <cuda_runtime.h>
#include <cstdint>

// PoolingLayer: out[p, f] = max_k features[idx[p,k], f]
// NP=50000, K=32, F=128. features: (100000,128) f32.
// idx: (50000,32) int32 (JAX x64-disabled downgrades jnp.int64 -> int32;
// confirmed by R3 pass with rel_err=0.0 on the int32 path).
//
// 1 warp per output point; lane l owns float4 #l of the row (512B/row, fully
// coalesced). features (51.2MB) is L2-resident -> kernel sits at the L2 BW
// roofline (~851MB total traffic).

#define NP_POINTS 50000
#define N_POINTS  100000
#define K_NEIGH   32
#define F_VEC4    32   // 128 floats = 32 float4

#define SZ_FEATURES 12800000   // 100000 * 128 f32
#define SZ_INDICES  1600000    // 50000 * 32

__global__ __launch_bounds__(256, 8)
void pool_max_kernel(const float4* __restrict__ feat,
                     const int* __restrict__ idx,
                     float4* __restrict__ out)
{
    const int gtid = blockIdx.x * blockDim.x + threadIdx.x;
    const int warp = gtid >> 5;
    const int lane = gtid & 31;
    if (warp >= NP_POINTS) return;

    // Coalesced, read-once index load (streaming hint keeps L2 for features).
    int my_idx = __ldcs(&idx[warp * K_NEIGH + lane]);
    // Clamp: a format surprise becomes rel_err, never an illegal access.
    my_idx = min(max(my_idx, 0), N_POINTS - 1);

    float4 m;
    m.x = -__int_as_float(0x7f800000);  // -inf
    m.y = m.x; m.z = m.x; m.w = m.x;

    #pragma unroll
    for (int k = 0; k < K_NEIGH; ++k) {
        const int j = __shfl_sync(0xffffffffu, my_idx, k);
        const float4 v = __ldg(&feat[(long long)j * F_VEC4 + lane]);
        m.x = fmaxf(m.x, v.x);
        m.y = fmaxf(m.y, v.y);
        m.z = fmaxf(m.z, v.z);
        m.w = fmaxf(m.w, v.w);
    }

    // Write-once output: streaming store, don't pollute L2.
    __stcs(&out[(long long)warp * F_VEC4 + lane], m);
}

extern "C" void kernel_launch(void* const* d_in, const int* in_sizes, int n_in,
                              void* d_out, int out_size)
{
    // Resolve inputs by element count (order-independent):
    //   features : 12800000 f32
    //   indices  : 1600000 int32
    const float4* feat = nullptr;
    const int*    idx  = nullptr;
    for (int i = 0; i < n_in; ++i) {
        if (in_sizes[i] == SZ_FEATURES)     feat = (const float4*)d_in[i];
        else if (in_sizes[i] == SZ_INDICES) idx  = (const int*)d_in[i];
    }
    if (!feat) feat = (const float4*)d_in[1];
    if (!idx)  idx  = (const int*)d_in[2];

    float4* out = (float4*)d_out;

    const int total_threads = NP_POINTS * 32;   // one warp per point
    const int block = 256;
    const int grid = (total_threads + block - 1) / block;  // 6250
    pool_max_kernel<<<grid, block>>>(feat, idx, out);
}